// round 1
// baseline (speedup 1.0000x reference)
#include <cuda_runtime.h>
#include <cuda_bf16.h>
#include <cstdint>

// Problem constants
#define BB   131072
#define HH   16
#define CC   32
#define HIDD 512
#define HPP  32
#define SKUD 64
#define TEMP_INV (1.0f/0.7f)
#define TIME_MAX 365.0f
#define LN_EPS 1e-3f

// Scratch (static device globals — allowed; no runtime allocation)
__device__ float g_agg[(size_t)BB * HIDD];     // aggregated  [B,512]
__device__ float g_hidden[(size_t)BB * HIDD];  // agg_hidden  [B,512]
__device__ float g_logits[(size_t)BB * HIDD];  // agg_hidden@Waa [B,512]
__device__ float g_beta[(size_t)BB * HIDD];    // sigmoid(sku@Wb) [B,512]
__device__ float g_cps[HH * CC];
__device__ float g_WaWo[SKUD];

// ---------------- packed f32x2 helpers ----------------
__device__ __forceinline__ unsigned long long pk2(float lo, float hi) {
    unsigned long long r;
    asm("mov.b64 %0, {%1, %2};" : "=l"(r) : "f"(lo), "f"(hi));
    return r;
}
__device__ __forceinline__ unsigned long long fma2(unsigned long long a,
                                                   unsigned long long b,
                                                   unsigned long long c) {
    unsigned long long d;
    asm("fma.rn.f32x2 %0, %1, %2, %3;" : "=l"(d) : "l"(a), "l"(b), "l"(c));
    return d;
}
__device__ __forceinline__ float2 upk2(unsigned long long v) {
    unsigned lo, hi;
    asm("mov.b64 {%0, %1}, %2;" : "=r"(lo), "=r"(hi) : "l"(v));
    return make_float2(__uint_as_float(lo), __uint_as_float(hi));
}

__device__ __forceinline__ float softplusf(float x) {
    return fmaxf(x, 0.0f) + log1pf(expf(-fabsf(x)));
}
__device__ __forceinline__ float mishf(float x) {
    return x * tanhf(softplusf(x));
}

// ---------------- K1: prep (cps cumsum + Wa@Wo fold) ----------------
__global__ void prep_kernel(const float* __restrict__ deltas,
                            const float* __restrict__ Wa,
                            const float* __restrict__ Wo) {
    int tid = threadIdx.x;
    int warp = tid >> 5, lane = tid & 31;
    if (warp < HH) {
        // inclusive scan of softplus(deltas[warp, :]) over lanes
        float p = softplusf(deltas[warp * CC + lane]);
        #pragma unroll
        for (int off = 1; off < 32; off <<= 1) {
            float v = __shfl_up_sync(0xffffffffu, p, off);
            if (lane >= off) p += v;
        }
        float total = __shfl_sync(0xffffffffu, p, 31);
        g_cps[warp * CC + lane] = p / total * TIME_MAX;
    }
    if (tid < SKUD) {
        float acc = 0.0f;
        for (int d = 0; d < HIDD; d++) acc += Wa[tid * HIDD + d] * Wo[d];
        g_WaWo[tid] = acc;
    }
}

// ---------------- K2: row features -> aggregated [B,512] ----------------
// grid(B/16, H), block 512 (16 warps, one b-row per warp; lane = changepoint c)
__global__ void __launch_bounds__(512)
rowfeat_kernel(const float* __restrict__ inputs,
               const float* __restrict__ ln_gamma,
               const float* __restrict__ ln_beta,
               const float* __restrict__ attn_w,
               const float* __restrict__ Wh) {
    __shared__ float sWh[CC * HPP];     // 32x32
    __shared__ float sGamma[CC], sBeta[CC], sCps[CC];
    __shared__ float sAw;

    const int h = blockIdx.y;
    const int tid = threadIdx.x;

    for (int i = tid; i < CC * HPP; i += blockDim.x)
        sWh[i] = Wh[h * CC * HPP + i];
    if (tid < CC) {
        sGamma[tid] = ln_gamma[h * CC + tid];
        sBeta[tid]  = ln_beta[h * CC + tid];
        sCps[tid]   = g_cps[h * CC + tid];
    }
    if (tid == 0) sAw = attn_w[h];
    __syncthreads();

    const int warp = tid >> 5, lane = tid & 31;
    const int b = blockIdx.x * 16 + warp;
    const unsigned FULL = 0xffffffffu;

    float x = inputs[b * HH + h];
    float f = fmaxf(x - sCps[lane], 0.0f);

    // LayerNorm over C (lanes)
    float s = f;
    #pragma unroll
    for (int m = 16; m > 0; m >>= 1) s += __shfl_xor_sync(FULL, s, m);
    float mu = s * (1.0f / CC);
    float d = f - mu;
    float v = d * d;
    #pragma unroll
    for (int m = 16; m > 0; m >>= 1) v += __shfl_xor_sync(FULL, v, m);
    float var = v * (1.0f / CC);
    float normed = d * rsqrtf(var + LN_EPS) * sGamma[lane] + sBeta[lane];

    // per-holiday attention softmax over C
    float logit = normed * sAw * TEMP_INV;
    float mx = logit;
    #pragma unroll
    for (int m = 16; m > 0; m >>= 1) mx = fmaxf(mx, __shfl_xor_sync(FULL, mx, m));
    float e = expf(logit - mx);
    float es = e;
    #pragma unroll
    for (int m = 16; m > 0; m >>= 1) es += __shfl_xor_sync(FULL, es, m);
    float att = normed * (e / es);

    // hid[d=lane] = mish( sum_c att[c] * Wh[h][c][lane] )
    float acc = 0.0f;
    #pragma unroll
    for (int c = 0; c < CC; c++) {
        float av = __shfl_sync(FULL, att, c);
        acc = fmaf(av, sWh[c * HPP + lane], acc);
    }
    g_agg[(size_t)b * HIDD + h * HPP + lane] = mishf(acc);
}

// ---------------- K3: SGEMM C = act(A[M,K] @ W[K,N]) ----------------
// BM=128 BN=64 BK=16, 256 threads, each 8x4 outputs, f32x2 accumulators
// ACT: 0=none 1=mish 2=sigmoid
template <int ACT>
__global__ void __launch_bounds__(256)
sgemm_kernel(const float* __restrict__ A, const float* __restrict__ W,
             float* __restrict__ C, int M, int K, int N) {
    __shared__ float As[16][128];
    __shared__ float Bs[16][64];

    const int tid = threadIdx.x;
    const int m0 = blockIdx.y * 128;
    const int n0 = blockIdx.x * 64;

    const int aRow = tid >> 2;        // 0..63
    const int aK4  = (tid & 3) * 4;   // 0,4,8,12
    const int bRow = tid >> 4;        // 0..15
    const int bN4  = (tid & 15) * 4;  // 0..60

    const int ty = tid >> 4;          // 0..15 -> M sub-block of 8
    const int tx = tid & 15;          // 0..15 -> N sub-block of 4
    const int mb = ty * 8;
    const int nb = tx * 4;

    unsigned long long acc[8][2];
    #pragma unroll
    for (int i = 0; i < 8; i++) { acc[i][0] = 0ull; acc[i][1] = 0ull; }

    for (int k0 = 0; k0 < K; k0 += 16) {
        // load A tile (2x float4 per thread), store transposed As[k][m]
        float4 a0 = *(const float4*)&A[(size_t)(m0 + aRow) * K + k0 + aK4];
        float4 a1 = *(const float4*)&A[(size_t)(m0 + aRow + 64) * K + k0 + aK4];
        As[aK4 + 0][aRow] = a0.x; As[aK4 + 1][aRow] = a0.y;
        As[aK4 + 2][aRow] = a0.z; As[aK4 + 3][aRow] = a0.w;
        As[aK4 + 0][aRow + 64] = a1.x; As[aK4 + 1][aRow + 64] = a1.y;
        As[aK4 + 2][aRow + 64] = a1.z; As[aK4 + 3][aRow + 64] = a1.w;
        // load B tile (1x float4 per thread)
        float4 bv = *(const float4*)&W[(size_t)(k0 + bRow) * N + n0 + bN4];
        *(float4*)&Bs[bRow][bN4] = bv;
        __syncthreads();

        #pragma unroll
        for (int kk = 0; kk < 16; kk++) {
            float4 b4 = *(const float4*)&Bs[kk][nb];
            unsigned long long b2_0 = pk2(b4.x, b4.y);
            unsigned long long b2_1 = pk2(b4.z, b4.w);
            #pragma unroll
            for (int i = 0; i < 8; i++) {
                float av = As[kk][mb + i];
                unsigned long long a2 = pk2(av, av);
                acc[i][0] = fma2(a2, b2_0, acc[i][0]);
                acc[i][1] = fma2(a2, b2_1, acc[i][1]);
            }
        }
        __syncthreads();
    }

    #pragma unroll
    for (int i = 0; i < 8; i++) {
        float2 p0 = upk2(acc[i][0]);
        float2 p1 = upk2(acc[i][1]);
        float4 o = make_float4(p0.x, p0.y, p1.x, p1.y);
        if (ACT == 1) {
            o.x = mishf(o.x); o.y = mishf(o.y); o.z = mishf(o.z); o.w = mishf(o.w);
        } else if (ACT == 2) {
            o.x = 1.0f / (1.0f + expf(-o.x));
            o.y = 1.0f / (1.0f + expf(-o.y));
            o.z = 1.0f / (1.0f + expf(-o.z));
            o.w = 1.0f / (1.0f + expf(-o.w));
        }
        *(float4*)&C[(size_t)(m0 + mb + i) * N + n0 + nb] = o;
    }
}

// ---------------- K4: epilogue — softmax over 512, final dot ----------------
// one warp per row; grid B/8, block 256
__global__ void __launch_bounds__(256)
epilogue_kernel(const float* __restrict__ sku,
                const float* __restrict__ Wo,
                float* __restrict__ out) {
    const int tid = threadIdx.x;
    const int warp = tid >> 5, lane = tid & 31;
    const int b = blockIdx.x * 8 + warp;
    const unsigned FULL = 0xffffffffu;

    const float* lg = &g_logits[(size_t)b * HIDD];
    const float* hd = &g_hidden[(size_t)b * HIDD];
    const float* bt = &g_beta[(size_t)b * HIDD];

    float lv[16];
    float mx = -3.4e38f;
    #pragma unroll
    for (int i = 0; i < 16; i++) {
        lv[i] = lg[lane + 32 * i] * TEMP_INV;
        mx = fmaxf(mx, lv[i]);
    }
    #pragma unroll
    for (int m = 16; m > 0; m >>= 1) mx = fmaxf(mx, __shfl_xor_sync(FULL, mx, m));

    float ssum = 0.0f, acc = 0.0f;
    #pragma unroll
    for (int i = 0; i < 16; i++) {
        int d = lane + 32 * i;
        float e = expf(lv[i] - mx);
        ssum += e;
        acc = fmaf(hd[d] * e, bt[d] * Wo[d], acc);
    }
    // sku . WaWo  (64 elems: 2 per lane)
    float sd = sku[b * SKUD + lane] * g_WaWo[lane]
             + sku[b * SKUD + 32 + lane] * g_WaWo[32 + lane];
    #pragma unroll
    for (int m = 16; m > 0; m >>= 1) {
        ssum += __shfl_xor_sync(FULL, ssum, m);
        acc  += __shfl_xor_sync(FULL, acc, m);
        sd   += __shfl_xor_sync(FULL, sd, m);
    }
    if (lane == 0) out[b] = acc / ssum + sd;
}

// ---------------- launch ----------------
extern "C" void kernel_launch(void* const* d_in, const int* in_sizes, int n_in,
                              void* d_out, int out_size) {
    const float* inputs   = (const float*)d_in[0];   // [B,16]
    const float* sku      = (const float*)d_in[1];   // [B,64]
    const float* deltas   = (const float*)d_in[2];   // [16,32]
    const float* ln_gamma = (const float*)d_in[3];   // [16,32]
    const float* ln_beta  = (const float*)d_in[4];   // [16,32]
    const float* attn_w   = (const float*)d_in[5];   // [16]
    const float* Wh       = (const float*)d_in[6];   // [16,32,32]
    const float* Wah      = (const float*)d_in[7];   // [512,512]
    const float* Waa      = (const float*)d_in[8];   // [512,512]
    const float* Wb       = (const float*)d_in[9];   // [64,512]
    const float* Wa       = (const float*)d_in[10];  // [64,512]
    const float* Wo       = (const float*)d_in[11];  // [512,1]
    float* out = (float*)d_out;

    float* agg;    cudaGetSymbolAddress((void**)&agg,    g_agg);
    float* hidden; cudaGetSymbolAddress((void**)&hidden, g_hidden);
    float* logits; cudaGetSymbolAddress((void**)&logits, g_logits);
    float* betab;  cudaGetSymbolAddress((void**)&betab,  g_beta);

    prep_kernel<<<1, 512>>>(deltas, Wa, Wo);

    dim3 g2(BB / 16, HH);
    rowfeat_kernel<<<g2, 512>>>(inputs, ln_gamma, ln_beta, attn_w, Wh);

    dim3 gg(HIDD / 64, BB / 128);
    sgemm_kernel<1><<<gg, 256>>>(agg,    Wah, hidden, BB, HIDD, HIDD);  // mish
    sgemm_kernel<0><<<gg, 256>>>(hidden, Waa, logits, BB, HIDD, HIDD);  // none
    sgemm_kernel<2><<<gg, 256>>>(sku,    Wb,  betab,  BB, SKUD, HIDD);  // sigmoid

    epilogue_kernel<<<BB / 8, 256>>>(sku, Wo, out);
}

// round 3
// speedup vs baseline: 1.7080x; 1.7080x over previous
#include <cuda_runtime.h>
#include <cuda_bf16.h>
#include <cstdint>

// Problem constants
#define BB   131072
#define HH   16
#define CC   32
#define HIDD 512
#define HPP  32
#define SKUD 64
#define TEMP_INV (1.0f/0.7f)
#define TIME_MAX 365.0f
#define LN_EPS 1e-3f

// ---------------- scratch (static device globals) ----------------
__device__ __nv_bfloat16 g_Ahi[(size_t)BB * HIDD];
__device__ __nv_bfloat16 g_Alo[(size_t)BB * HIDD];
__device__ __nv_bfloat16 g_Hhi[(size_t)BB * HIDD];
__device__ __nv_bfloat16 g_Hlo[(size_t)BB * HIDD];
__device__ float g_hidden[(size_t)BB * HIDD];
__device__ float g_logits[(size_t)BB * HIDD];
__device__ float g_beta[(size_t)BB * HIDD];
__device__ __nv_bfloat16 g_skuhi[(size_t)BB * SKUD];
__device__ __nv_bfloat16 g_skulo[(size_t)BB * SKUD];
__device__ __nv_bfloat16 g_WahT_hi[HIDD * HIDD], g_WahT_lo[HIDD * HIDD];
__device__ __nv_bfloat16 g_WaaT_hi[HIDD * HIDD], g_WaaT_lo[HIDD * HIDD];
__device__ __nv_bfloat16 g_WbT_hi[HIDD * SKUD], g_WbT_lo[HIDD * SKUD];
__device__ float g_cps[HH * CC];
__device__ float g_WaWo[SKUD];

// ---------------- helpers ----------------
__device__ __forceinline__ uint32_t smem_u32(const void* p) {
    uint32_t a;
    asm("{ .reg .u64 t; cvta.to.shared.u64 t, %1; cvt.u32.u64 %0, t; }" : "=r"(a) : "l"(p));
    return a;
}
#define CP16(dst, src) \
    asm volatile("cp.async.cg.shared.global [%0], [%1], 16;" :: "r"(dst), "l"(src))
#define CP_COMMIT() asm volatile("cp.async.commit_group;" ::: "memory")
template <int N>
__device__ __forceinline__ void cp_wait() {
    asm volatile("cp.async.wait_group %0;" :: "n"(N) : "memory");
}
#define LDMX4(d0, d1, d2, d3, addr) \
    asm volatile("ldmatrix.sync.aligned.m8n8.x4.shared.b16 {%0,%1,%2,%3}, [%4];" \
                 : "=r"(d0), "=r"(d1), "=r"(d2), "=r"(d3) : "r"(addr))
#define MMA16816(c0, c1, c2, c3, a0, a1, a2, a3, b0, b1) \
    asm volatile("mma.sync.aligned.m16n8k16.row.col.f32.bf16.bf16.f32 " \
                 "{%0,%1,%2,%3}, {%4,%5,%6,%7}, {%8,%9}, {%0,%1,%2,%3};" \
                 : "+f"(c0), "+f"(c1), "+f"(c2), "+f"(c3) \
                 : "r"(a0), "r"(a1), "r"(a2), "r"(a3), "r"(b0), "r"(b1))

__device__ __forceinline__ float softplusf(float x) {
    return fmaxf(x, 0.0f) + log1pf(expf(-fabsf(x)));
}
__device__ __forceinline__ float mishf(float x) {
    float t = __expf(fminf(x, 20.0f));
    float u = t * (t + 2.0f);
    float y = x * (u / (u + 2.0f));
    return (x > 20.0f) ? x : y;
}
__device__ __forceinline__ void split_bf16(float v, __nv_bfloat16& hi, __nv_bfloat16& lo) {
    hi = __float2bfloat16(v);
    lo = __float2bfloat16(v - __bfloat162float(hi));
}

// ---------------- K1: prep ----------------
__global__ void prep_kernel(const float* __restrict__ deltas,
                            const float* __restrict__ Wa,
                            const float* __restrict__ Wo) {
    int tid = threadIdx.x;
    int warp = tid >> 5, lane = tid & 31;
    if (warp < HH) {
        float p = softplusf(deltas[warp * CC + lane]);
        #pragma unroll
        for (int off = 1; off < 32; off <<= 1) {
            float v = __shfl_up_sync(0xffffffffu, p, off);
            if (lane >= off) p += v;
        }
        float total = __shfl_sync(0xffffffffu, p, 31);
        g_cps[warp * CC + lane] = p / total * TIME_MAX;
    }
    if (tid < SKUD) {
        float acc = 0.0f;
        for (int d = 0; d < HIDD; d++) acc += Wa[tid * HIDD + d] * Wo[d];
        g_WaWo[tid] = acc;
    }
}

// ---------------- weight transpose + split: out[n][k] = W[k][n] ----------------
__global__ void wconv_kernel(const float* __restrict__ W,
                             __nv_bfloat16* __restrict__ hi,
                             __nv_bfloat16* __restrict__ lo, int K, int N) {
    int n = blockIdx.x;
    for (int k = threadIdx.x; k < K; k += blockDim.x) {
        float v = W[(size_t)k * N + n];
        __nv_bfloat16 h, l;
        split_bf16(v, h, l);
        hi[(size_t)n * K + k] = h;
        lo[(size_t)n * K + k] = l;
    }
}

__global__ void skuconv_kernel(const float* __restrict__ sku) {
    size_t i = (size_t)blockIdx.x * blockDim.x + threadIdx.x;
    if (i < (size_t)BB * SKUD) {
        __nv_bfloat16 h, l;
        split_bf16(sku[i], h, l);
        g_skuhi[i] = h;
        g_skulo[i] = l;
    }
}

// ---------------- K2: row features -> bf16 hi/lo aggregated ----------------
__global__ void __launch_bounds__(512)
rowfeat_kernel(const float* __restrict__ inputs,
               const float* __restrict__ ln_gamma,
               const float* __restrict__ ln_beta,
               const float* __restrict__ attn_w,
               const float* __restrict__ Wh) {
    __shared__ float sWh[CC * HPP];
    __shared__ float sGamma[CC], sBeta[CC], sCps[CC];
    __shared__ float sAw;

    const int h = blockIdx.y;
    const int tid = threadIdx.x;

    for (int i = tid; i < CC * HPP; i += blockDim.x)
        sWh[i] = Wh[h * CC * HPP + i];
    if (tid < CC) {
        sGamma[tid] = ln_gamma[h * CC + tid];
        sBeta[tid]  = ln_beta[h * CC + tid];
        sCps[tid]   = g_cps[h * CC + tid];
    }
    if (tid == 0) sAw = attn_w[h];
    __syncthreads();

    const int warp = tid >> 5, lane = tid & 31;
    const int b = blockIdx.x * 16 + warp;
    const unsigned FULL = 0xffffffffu;

    float x = inputs[b * HH + h];
    float f = fmaxf(x - sCps[lane], 0.0f);

    float s = f;
    #pragma unroll
    for (int m = 16; m > 0; m >>= 1) s += __shfl_xor_sync(FULL, s, m);
    float mu = s * (1.0f / CC);
    float d = f - mu;
    float v = d * d;
    #pragma unroll
    for (int m = 16; m > 0; m >>= 1) v += __shfl_xor_sync(FULL, v, m);
    float var = v * (1.0f / CC);
    float normed = d * rsqrtf(var + LN_EPS) * sGamma[lane] + sBeta[lane];

    float logit = normed * sAw * TEMP_INV;
    float mx = logit;
    #pragma unroll
    for (int m = 16; m > 0; m >>= 1) mx = fmaxf(mx, __shfl_xor_sync(FULL, mx, m));
    float e = __expf(logit - mx);
    float es = e;
    #pragma unroll
    for (int m = 16; m > 0; m >>= 1) es += __shfl_xor_sync(FULL, es, m);
    float att = normed * (e / es);

    float acc = 0.0f;
    #pragma unroll
    for (int c = 0; c < CC; c++) {
        float av = __shfl_sync(FULL, att, c);
        acc = fmaf(av, sWh[c * HPP + lane], acc);
    }
    float val = mishf(acc);
    __nv_bfloat16 hb, lb;
    split_bf16(val, hb, lb);
    size_t idx = (size_t)b * HIDD + h * HPP + lane;
    g_Ahi[idx] = hb;
    g_Alo[idx] = lb;
}

// ---------------- K3: HMMA GEMM ----------------
// C[M,512] = act( A[M,KG] @ B[512,KG]^T ), bf16 3-product split, fp32 accum.
// BM=128 BN=128 BK=32, 256 threads, warp grid 2(M)x4(N), warp tile 64x32.
// smem row stride 40 halves (80B) -> conflict-free ldmatrix.
#define GROW 80                      // bytes per smem row
#define TILE_A 10240                 // 128 rows * 80B
#define STAGE 40960                  // Ahi+Alo+Bhi+Blo
#define SOFF_AHI 0
#define SOFF_ALO 10240
#define SOFF_BHI 20480
#define SOFF_BLO 30720
#define GEMM_SMEM (2 * STAGE)        // 81920

template <int ACT, bool WRITE_SPLIT>
__global__ void __launch_bounds__(256)
gemm_mma(const __nv_bfloat16* __restrict__ Ahi, const __nv_bfloat16* __restrict__ Alo,
         const __nv_bfloat16* __restrict__ Bhi, const __nv_bfloat16* __restrict__ Blo,
         float* __restrict__ Cf,
         __nv_bfloat16* __restrict__ Chi, __nv_bfloat16* __restrict__ Clo,
         int KG) {
    extern __shared__ char smem[];
    const uint32_t sb = smem_u32(smem);
    const int tid = threadIdx.x;
    const int wid = tid >> 5, lane = tid & 31;
    const int wm = wid & 1, wn = wid >> 1;      // warp grid 2 x 4
    const int m0 = blockIdx.y * 128;
    const int n0 = blockIdx.x * 128;
    const int KT = KG >> 5;

    float c[4][4][4];
    #pragma unroll
    for (int i = 0; i < 4; i++)
        #pragma unroll
        for (int j = 0; j < 4; j++)
            #pragma unroll
            for (int q = 0; q < 4; q++) c[i][j][q] = 0.0f;

    // load helper (issues 8 CP16 per thread): tile kt into stage s
    auto load_tile = [&](int s, int kt) {
        const uint32_t base = sb + s * STAGE;
        #pragma unroll
        for (int i = 0; i < 2; i++) {
            int idx = i * 256 + tid;
            int row = idx >> 2, ch = idx & 3;
            uint32_t so = (uint32_t)(row * GROW + ch * 16);
            size_t go = (size_t)(m0 + row) * KG + kt * 32 + ch * 8;
            CP16(base + SOFF_AHI + so, Ahi + go);
            CP16(base + SOFF_ALO + so, Alo + go);
            size_t gb = (size_t)(n0 + row) * KG + kt * 32 + ch * 8;
            CP16(base + SOFF_BHI + so, Bhi + gb);
            CP16(base + SOFF_BLO + so, Blo + gb);
        }
        CP_COMMIT();
    };

    load_tile(0, 0);

    for (int kt = 0; kt < KT; kt++) {
        if (kt + 1 < KT) {
            load_tile((kt + 1) & 1, kt + 1);
            cp_wait<1>();
        } else {
            cp_wait<0>();
        }
        __syncthreads();

        const uint32_t st = sb + (kt & 1) * STAGE;
        const uint32_t lrow = (uint32_t)(lane & 15);
        const uint32_t lcolB = (uint32_t)((lane >> 4) * 16);

        #pragma unroll
        for (int ks = 0; ks < 2; ks++) {
            const uint32_t kb = ks * 32 + lcolB;  // byte offset along k
            // B fragments: 2 x4-ldmatrix per hi/lo, covering n16 each
            uint32_t bh[2][4], bl[2][4];
            #pragma unroll
            for (int p = 0; p < 2; p++) {
                uint32_t ro = (uint32_t)((wn * 32 + p * 16 + lrow) * GROW) + kb;
                LDMX4(bh[p][0], bh[p][1], bh[p][2], bh[p][3], st + SOFF_BHI + ro);
                LDMX4(bl[p][0], bl[p][1], bl[p][2], bl[p][3], st + SOFF_BLO + ro);
            }
            #pragma unroll
            for (int mt = 0; mt < 4; mt++) {
                uint32_t ro = (uint32_t)((wm * 64 + mt * 16 + lrow) * GROW) + kb;
                uint32_t ah0, ah1, ah2, ah3, al0, al1, al2, al3;
                LDMX4(ah0, ah1, ah2, ah3, st + SOFF_AHI + ro);
                LDMX4(al0, al1, al2, al3, st + SOFF_ALO + ro);
                #pragma unroll
                for (int nt = 0; nt < 4; nt++) {
                    const int p = nt >> 1, j = nt & 1;
                    float* cc = c[mt][nt];
                    MMA16816(cc[0], cc[1], cc[2], cc[3],
                             ah0, ah1, ah2, ah3, bh[p][j], bh[p][j + 2]);
                    MMA16816(cc[0], cc[1], cc[2], cc[3],
                             ah0, ah1, ah2, ah3, bl[p][j], bl[p][j + 2]);
                    MMA16816(cc[0], cc[1], cc[2], cc[3],
                             al0, al1, al2, al3, bh[p][j], bh[p][j + 2]);
                }
            }
        }
        __syncthreads();
    }

    // epilogue
    #pragma unroll
    for (int mt = 0; mt < 4; mt++) {
        #pragma unroll
        for (int nt = 0; nt < 4; nt++) {
            #pragma unroll
            for (int i = 0; i < 2; i++) {
                int gm = m0 + wm * 64 + mt * 16 + (lane >> 2) + i * 8;
                int gn = n0 + wn * 32 + nt * 8 + (lane & 3) * 2;
                float x0 = c[mt][nt][i * 2];
                float x1 = c[mt][nt][i * 2 + 1];
                if (ACT == 1) { x0 = mishf(x0); x1 = mishf(x1); }
                else if (ACT == 2) {
                    x0 = 1.0f / (1.0f + __expf(-x0));
                    x1 = 1.0f / (1.0f + __expf(-x1));
                }
                size_t o = (size_t)gm * HIDD + gn;
                *(float2*)&Cf[o] = make_float2(x0, x1);
                if (WRITE_SPLIT) {
                    __nv_bfloat16 h0, l0, h1, l1;
                    split_bf16(x0, h0, l0);
                    split_bf16(x1, h1, l1);
                    *(__nv_bfloat162*)&Chi[o] = __halves2bfloat162(h0, h1);
                    *(__nv_bfloat162*)&Clo[o] = __halves2bfloat162(l0, l1);
                }
            }
        }
    }
}

// ---------------- K4: final epilogue ----------------
__global__ void __launch_bounds__(256)
epilogue_kernel(const float* __restrict__ sku,
                const float* __restrict__ Wo,
                float* __restrict__ out) {
    const int tid = threadIdx.x;
    const int warp = tid >> 5, lane = tid & 31;
    const int b = blockIdx.x * 8 + warp;
    const unsigned FULL = 0xffffffffu;

    const float* lg = &g_logits[(size_t)b * HIDD];
    const float* hd = &g_hidden[(size_t)b * HIDD];
    const float* bt = &g_beta[(size_t)b * HIDD];

    float lv[16];
    float mx = -3.4e38f;
    #pragma unroll
    for (int i = 0; i < 16; i++) {
        lv[i] = lg[lane + 32 * i] * TEMP_INV;
        mx = fmaxf(mx, lv[i]);
    }
    #pragma unroll
    for (int m = 16; m > 0; m >>= 1) mx = fmaxf(mx, __shfl_xor_sync(FULL, mx, m));

    float ssum = 0.0f, acc = 0.0f;
    #pragma unroll
    for (int i = 0; i < 16; i++) {
        int d = lane + 32 * i;
        float e = __expf(lv[i] - mx);
        ssum += e;
        acc = fmaf(hd[d] * e, bt[d] * Wo[d], acc);
    }
    float sd = sku[b * SKUD + lane] * g_WaWo[lane]
             + sku[b * SKUD + 32 + lane] * g_WaWo[32 + lane];
    #pragma unroll
    for (int m = 16; m > 0; m >>= 1) {
        ssum += __shfl_xor_sync(FULL, ssum, m);
        acc  += __shfl_xor_sync(FULL, acc, m);
        sd   += __shfl_xor_sync(FULL, sd, m);
    }
    if (lane == 0) out[b] = acc / ssum + sd;
}

// ---------------- launch ----------------
extern "C" void kernel_launch(void* const* d_in, const int* in_sizes, int n_in,
                              void* d_out, int out_size) {
    const float* inputs   = (const float*)d_in[0];
    const float* sku      = (const float*)d_in[1];
    const float* deltas   = (const float*)d_in[2];
    const float* ln_gamma = (const float*)d_in[3];
    const float* ln_beta  = (const float*)d_in[4];
    const float* attn_w   = (const float*)d_in[5];
    const float* Wh       = (const float*)d_in[6];
    const float* Wah      = (const float*)d_in[7];
    const float* Waa      = (const float*)d_in[8];
    const float* Wb       = (const float*)d_in[9];
    const float* Wa       = (const float*)d_in[10];
    const float* Wo       = (const float*)d_in[11];
    float* out = (float*)d_out;

    __nv_bfloat16 *ahi, *alo, *hhi, *hlo, *skh, *skl;
    __nv_bfloat16 *wahh, *wahl, *waah, *waal, *wbh, *wbl;
    float *hidden, *logits, *betab;
    cudaGetSymbolAddress((void**)&ahi, g_Ahi);
    cudaGetSymbolAddress((void**)&alo, g_Alo);
    cudaGetSymbolAddress((void**)&hhi, g_Hhi);
    cudaGetSymbolAddress((void**)&hlo, g_Hlo);
    cudaGetSymbolAddress((void**)&skh, g_skuhi);
    cudaGetSymbolAddress((void**)&skl, g_skulo);
    cudaGetSymbolAddress((void**)&wahh, g_WahT_hi);
    cudaGetSymbolAddress((void**)&wahl, g_WahT_lo);
    cudaGetSymbolAddress((void**)&waah, g_WaaT_hi);
    cudaGetSymbolAddress((void**)&waal, g_WaaT_lo);
    cudaGetSymbolAddress((void**)&wbh, g_WbT_hi);
    cudaGetSymbolAddress((void**)&wbl, g_WbT_lo);
    cudaGetSymbolAddress((void**)&hidden, g_hidden);
    cudaGetSymbolAddress((void**)&logits, g_logits);
    cudaGetSymbolAddress((void**)&betab, g_beta);

    cudaFuncSetAttribute(gemm_mma<1, true>,  cudaFuncAttributeMaxDynamicSharedMemorySize, GEMM_SMEM);
    cudaFuncSetAttribute(gemm_mma<0, false>, cudaFuncAttributeMaxDynamicSharedMemorySize, GEMM_SMEM);
    cudaFuncSetAttribute(gemm_mma<2, false>, cudaFuncAttributeMaxDynamicSharedMemorySize, GEMM_SMEM);

    prep_kernel<<<1, 512>>>(deltas, Wa, Wo);
    wconv_kernel<<<512, 128>>>(Wah, wahh, wahl, HIDD, HIDD);
    wconv_kernel<<<512, 128>>>(Waa, waah, waal, HIDD, HIDD);
    wconv_kernel<<<512, 64>>>(Wb, wbh, wbl, SKUD, HIDD);
    skuconv_kernel<<<(BB * SKUD) / 256, 256>>>(sku);

    dim3 g2(BB / 16, HH);
    rowfeat_kernel<<<g2, 512>>>(inputs, ln_gamma, ln_beta, attn_w, Wh);

    dim3 gg(4, BB / 128);
    gemm_mma<1, true><<<gg, 256, GEMM_SMEM>>>(ahi, alo, wahh, wahl, hidden, hhi, hlo, HIDD);
    gemm_mma<0, false><<<gg, 256, GEMM_SMEM>>>(hhi, hlo, waah, waal, logits, nullptr, nullptr, HIDD);
    gemm_mma<2, false><<<gg, 256, GEMM_SMEM>>>(skh, skl, wbh, wbl, betab, nullptr, nullptr, SKUD);

    epilogue_kernel<<<BB / 8, 256>>>(sku, Wo, out);
}

// round 4
// speedup vs baseline: 1.7536x; 1.0267x over previous
#include <cuda_runtime.h>
#include <cuda_bf16.h>
#include <cstdint>

// Problem constants
#define BB   131072
#define HH   16
#define CC   32
#define HIDD 512
#define HPP  32
#define SKUD 64
#define TEMP_INV (1.0f/0.7f)
#define TIME_MAX 365.0f
#define LN_EPS 1e-3f

// ---------------- scratch ----------------
__device__ __nv_bfloat16 g_Ahi[(size_t)BB * HIDD];
__device__ __nv_bfloat16 g_Alo[(size_t)BB * HIDD];
__device__ __nv_bfloat16 g_Hhi[(size_t)BB * HIDD];
__device__ __nv_bfloat16 g_Hlo[(size_t)BB * HIDD];
__device__ float g_beta[(size_t)BB * HIDD];
__device__ __nv_bfloat16 g_skuhi[(size_t)BB * SKUD];
__device__ __nv_bfloat16 g_skulo[(size_t)BB * SKUD];
__device__ __nv_bfloat16 g_WahT_hi[HIDD * HIDD], g_WahT_lo[HIDD * HIDD];
__device__ __nv_bfloat16 g_WaaT_hi[HIDD * HIDD], g_WaaT_lo[HIDD * HIDD];
__device__ __nv_bfloat16 g_WbT_hi[HIDD * SKUD], g_WbT_lo[HIDD * SKUD];
__device__ float g_cps[HH * CC];
__device__ float g_WaWo[SKUD];

// ---------------- helpers ----------------
__device__ __forceinline__ uint32_t smem_u32(const void* p) {
    uint32_t a;
    asm("{ .reg .u64 t; cvta.to.shared.u64 t, %1; cvt.u32.u64 %0, t; }" : "=r"(a) : "l"(p));
    return a;
}
#define CP16(dst, src) \
    asm volatile("cp.async.cg.shared.global [%0], [%1], 16;" :: "r"(dst), "l"(src))
#define CP_COMMIT() asm volatile("cp.async.commit_group;" ::: "memory")
template <int N>
__device__ __forceinline__ void cp_wait() {
    asm volatile("cp.async.wait_group %0;" :: "n"(N) : "memory");
}
#define LDMX4(d0, d1, d2, d3, addr) \
    asm volatile("ldmatrix.sync.aligned.m8n8.x4.shared.b16 {%0,%1,%2,%3}, [%4];" \
                 : "=r"(d0), "=r"(d1), "=r"(d2), "=r"(d3) : "r"(addr))
#define MMA16816(c0, c1, c2, c3, a0, a1, a2, a3, b0, b1) \
    asm volatile("mma.sync.aligned.m16n8k16.row.col.f32.bf16.bf16.f32 " \
                 "{%0,%1,%2,%3}, {%4,%5,%6,%7}, {%8,%9}, {%0,%1,%2,%3};" \
                 : "+f"(c0), "+f"(c1), "+f"(c2), "+f"(c3) \
                 : "r"(a0), "r"(a1), "r"(a2), "r"(a3), "r"(b0), "r"(b1))

__device__ __forceinline__ float softplusf(float x) {
    return fmaxf(x, 0.0f) + log1pf(expf(-fabsf(x)));
}
__device__ __forceinline__ float mishf(float x) {
    float t = __expf(fminf(x, 20.0f));
    float u = t * (t + 2.0f);
    float y = x * (u / (u + 2.0f));
    return (x > 20.0f) ? x : y;
}
__device__ __forceinline__ void split_bf16(float v, __nv_bfloat16& hi, __nv_bfloat16& lo) {
    hi = __float2bfloat16(v);
    lo = __float2bfloat16(v - __bfloat162float(hi));
}

// ---------------- K1: prep ----------------
__global__ void prep_kernel(const float* __restrict__ deltas,
                            const float* __restrict__ Wa,
                            const float* __restrict__ Wo) {
    int tid = threadIdx.x;
    int warp = tid >> 5, lane = tid & 31;
    if (warp < HH) {
        float p = softplusf(deltas[warp * CC + lane]);
        #pragma unroll
        for (int off = 1; off < 32; off <<= 1) {
            float v = __shfl_up_sync(0xffffffffu, p, off);
            if (lane >= off) p += v;
        }
        float total = __shfl_sync(0xffffffffu, p, 31);
        g_cps[warp * CC + lane] = p / total * TIME_MAX;
    }
    if (tid < SKUD) {
        float acc = 0.0f;
        for (int d = 0; d < HIDD; d++) acc += Wa[tid * HIDD + d] * Wo[d];
        g_WaWo[tid] = acc;
    }
}

// ---------------- weight transpose + split ----------------
__global__ void wconv_kernel(const float* __restrict__ W,
                             __nv_bfloat16* __restrict__ hi,
                             __nv_bfloat16* __restrict__ lo, int K, int N) {
    int n = blockIdx.x;
    for (int k = threadIdx.x; k < K; k += blockDim.x) {
        float v = W[(size_t)k * N + n];
        __nv_bfloat16 h, l;
        split_bf16(v, h, l);
        hi[(size_t)n * K + k] = h;
        lo[(size_t)n * K + k] = l;
    }
}

__global__ void skuconv_kernel(const float* __restrict__ sku) {
    size_t i = (size_t)blockIdx.x * blockDim.x + threadIdx.x;
    if (i < (size_t)BB * SKUD) {
        __nv_bfloat16 h, l;
        split_bf16(sku[i], h, l);
        g_skuhi[i] = h;
        g_skulo[i] = l;
    }
}

// ---------------- K2: row features ----------------
__global__ void __launch_bounds__(512)
rowfeat_kernel(const float* __restrict__ inputs,
               const float* __restrict__ ln_gamma,
               const float* __restrict__ ln_beta,
               const float* __restrict__ attn_w,
               const float* __restrict__ Wh) {
    __shared__ float sWh[CC * HPP];
    __shared__ float sGamma[CC], sBeta[CC], sCps[CC];
    __shared__ float sAw;

    const int h = blockIdx.y;
    const int tid = threadIdx.x;

    for (int i = tid; i < CC * HPP; i += blockDim.x)
        sWh[i] = Wh[h * CC * HPP + i];
    if (tid < CC) {
        sGamma[tid] = ln_gamma[h * CC + tid];
        sBeta[tid]  = ln_beta[h * CC + tid];
        sCps[tid]   = g_cps[h * CC + tid];
    }
    if (tid == 0) sAw = attn_w[h];
    __syncthreads();

    const int warp = tid >> 5, lane = tid & 31;
    const int b = blockIdx.x * 16 + warp;
    const unsigned FULL = 0xffffffffu;

    float x = inputs[b * HH + h];
    float f = fmaxf(x - sCps[lane], 0.0f);

    float s = f;
    #pragma unroll
    for (int m = 16; m > 0; m >>= 1) s += __shfl_xor_sync(FULL, s, m);
    float mu = s * (1.0f / CC);
    float d = f - mu;
    float v = d * d;
    #pragma unroll
    for (int m = 16; m > 0; m >>= 1) v += __shfl_xor_sync(FULL, v, m);
    float var = v * (1.0f / CC);
    float normed = d * rsqrtf(var + LN_EPS) * sGamma[lane] + sBeta[lane];

    float logit = normed * sAw * TEMP_INV;
    float mx = logit;
    #pragma unroll
    for (int m = 16; m > 0; m >>= 1) mx = fmaxf(mx, __shfl_xor_sync(FULL, mx, m));
    float e = __expf(logit - mx);
    float es = e;
    #pragma unroll
    for (int m = 16; m > 0; m >>= 1) es += __shfl_xor_sync(FULL, es, m);
    float att = normed * (e / es);

    float acc = 0.0f;
    #pragma unroll
    for (int c = 0; c < CC; c++) {
        float av = __shfl_sync(FULL, att, c);
        acc = fmaf(av, sWh[c * HPP + lane], acc);
    }
    float val = mishf(acc);
    __nv_bfloat16 hb, lb;
    split_bf16(val, hb, lb);
    size_t idx = (size_t)b * HIDD + h * HPP + lane;
    g_Ahi[idx] = hb;
    g_Alo[idx] = lb;
}

// ---------------- K3: tiled HMMA GEMM (gemm1 / gemm3) ----------------
#define GROW 80
#define STAGE 40960
#define SOFF_AHI 0
#define SOFF_ALO 10240
#define SOFF_BHI 20480
#define SOFF_BLO 30720
#define GEMM_SMEM (2 * STAGE)

template <int ACT, bool WRITE_SPLIT, bool WRITE_F32>
__global__ void __launch_bounds__(256, 2)
gemm_mma(const __nv_bfloat16* __restrict__ Ahi, const __nv_bfloat16* __restrict__ Alo,
         const __nv_bfloat16* __restrict__ Bhi, const __nv_bfloat16* __restrict__ Blo,
         float* __restrict__ Cf,
         __nv_bfloat16* __restrict__ Chi, __nv_bfloat16* __restrict__ Clo,
         int KG) {
    extern __shared__ char smem[];
    const uint32_t sb = smem_u32(smem);
    const int tid = threadIdx.x;
    const int wid = tid >> 5, lane = tid & 31;
    const int wm = wid & 1, wn = wid >> 1;
    const int m0 = blockIdx.y * 128;
    const int n0 = blockIdx.x * 128;
    const int KT = KG >> 5;

    float c[4][4][4];
    #pragma unroll
    for (int i = 0; i < 4; i++)
        #pragma unroll
        for (int j = 0; j < 4; j++)
            #pragma unroll
            for (int q = 0; q < 4; q++) c[i][j][q] = 0.0f;

    auto load_tile = [&](int s, int kt) {
        const uint32_t base = sb + s * STAGE;
        #pragma unroll
        for (int i = 0; i < 2; i++) {
            int idx = i * 256 + tid;
            int row = idx >> 2, ch = idx & 3;
            uint32_t so = (uint32_t)(row * GROW + ch * 16);
            size_t go = (size_t)(m0 + row) * KG + kt * 32 + ch * 8;
            CP16(base + SOFF_AHI + so, Ahi + go);
            CP16(base + SOFF_ALO + so, Alo + go);
            size_t gb = (size_t)(n0 + row) * KG + kt * 32 + ch * 8;
            CP16(base + SOFF_BHI + so, Bhi + gb);
            CP16(base + SOFF_BLO + so, Blo + gb);
        }
        CP_COMMIT();
    };

    load_tile(0, 0);

    for (int kt = 0; kt < KT; kt++) {
        if (kt + 1 < KT) {
            load_tile((kt + 1) & 1, kt + 1);
            cp_wait<1>();
        } else {
            cp_wait<0>();
        }
        __syncthreads();

        const uint32_t st = sb + (kt & 1) * STAGE;
        const uint32_t lrow = (uint32_t)(lane & 15);
        const uint32_t lcolB = (uint32_t)((lane >> 4) * 16);

        #pragma unroll
        for (int ks = 0; ks < 2; ks++) {
            const uint32_t kb = ks * 32 + lcolB;
            uint32_t bh[2][4], bl[2][4];
            #pragma unroll
            for (int p = 0; p < 2; p++) {
                uint32_t ro = (uint32_t)((wn * 32 + p * 16 + lrow) * GROW) + kb;
                LDMX4(bh[p][0], bh[p][1], bh[p][2], bh[p][3], st + SOFF_BHI + ro);
                LDMX4(bl[p][0], bl[p][1], bl[p][2], bl[p][3], st + SOFF_BLO + ro);
            }
            #pragma unroll
            for (int mt = 0; mt < 4; mt++) {
                uint32_t ro = (uint32_t)((wm * 64 + mt * 16 + lrow) * GROW) + kb;
                uint32_t ah0, ah1, ah2, ah3, al0, al1, al2, al3;
                LDMX4(ah0, ah1, ah2, ah3, st + SOFF_AHI + ro);
                LDMX4(al0, al1, al2, al3, st + SOFF_ALO + ro);
                #pragma unroll
                for (int nt = 0; nt < 4; nt++) {
                    const int p = nt >> 1, j = nt & 1;
                    float* cc = c[mt][nt];
                    MMA16816(cc[0], cc[1], cc[2], cc[3],
                             ah0, ah1, ah2, ah3, bh[p][j], bh[p][j + 2]);
                    MMA16816(cc[0], cc[1], cc[2], cc[3],
                             ah0, ah1, ah2, ah3, bl[p][j], bl[p][j + 2]);
                    MMA16816(cc[0], cc[1], cc[2], cc[3],
                             al0, al1, al2, al3, bh[p][j], bh[p][j + 2]);
                }
            }
        }
        __syncthreads();
    }

    #pragma unroll
    for (int mt = 0; mt < 4; mt++) {
        #pragma unroll
        for (int nt = 0; nt < 4; nt++) {
            #pragma unroll
            for (int i = 0; i < 2; i++) {
                int gm = m0 + wm * 64 + mt * 16 + (lane >> 2) + i * 8;
                int gn = n0 + wn * 32 + nt * 8 + (lane & 3) * 2;
                float x0 = c[mt][nt][i * 2];
                float x1 = c[mt][nt][i * 2 + 1];
                if (ACT == 1) { x0 = mishf(x0); x1 = mishf(x1); }
                else if (ACT == 2) {
                    x0 = 1.0f / (1.0f + __expf(-x0));
                    x1 = 1.0f / (1.0f + __expf(-x1));
                }
                size_t o = (size_t)gm * HIDD + gn;
                if (WRITE_F32)
                    *(float2*)&Cf[o] = make_float2(x0, x1);
                if (WRITE_SPLIT) {
                    __nv_bfloat16 h0, l0, h1, l1;
                    split_bf16(x0, h0, l0);
                    split_bf16(x1, h1, l1);
                    *(__nv_bfloat162*)&Chi[o] = __halves2bfloat162(h0, h1);
                    *(__nv_bfloat162*)&Clo[o] = __halves2bfloat162(l0, l1);
                }
            }
        }
    }
}

// ---------------- K4: fused GEMM2 + softmax epilogue ----------------
// BM=64, BN=512 (full row), BK=32, 512 threads (16 warps, 2x8 grid, warp 32x64).
#define E_GROW 80
#define E_AHI 0
#define E_ALO 5120
#define E_BHI 10240
#define E_BLO 51200
#define E_STAGE 92160
#define E_LSTRIDE 520
#define E_WO_OFF (2 * E_STAGE)            // 184320
#define E_SMEM (E_WO_OFF + 2048)          // 186368

__global__ void __launch_bounds__(512)
gemm2e(const __nv_bfloat16* __restrict__ Ahi, const __nv_bfloat16* __restrict__ Alo,
       const __nv_bfloat16* __restrict__ Bhi, const __nv_bfloat16* __restrict__ Blo,
       const float* __restrict__ beta, const float* __restrict__ sku,
       const float* __restrict__ Wo, float* __restrict__ out) {
    extern __shared__ char smem[];
    const uint32_t sb = smem_u32(smem);
    float* sL = (float*)smem;                          // logits staging (post-loop)
    float* sWo = (float*)(smem + E_WO_OFF);
    const int tid = threadIdx.x;
    const int wid = tid >> 5, lane = tid & 31;
    const int wm = wid & 1, wn = wid >> 1;             // 2 x 8
    const int m0 = blockIdx.x * 64;
    const unsigned FULL = 0xffffffffu;

    sWo[tid] = Wo[tid];

    float c[2][8][4];
    #pragma unroll
    for (int i = 0; i < 2; i++)
        #pragma unroll
        for (int j = 0; j < 8; j++)
            #pragma unroll
            for (int q = 0; q < 4; q++) c[i][j][q] = 0.0f;

    auto load_tile = [&](int s, int kt) {
        const uint32_t base = sb + s * E_STAGE;
        // B: 512 rows x 4 chunks, hi+lo
        #pragma unroll
        for (int i = 0; i < 4; i++) {
            int idx = i * 512 + tid;
            int row = idx >> 2, ch = idx & 3;
            uint32_t so = (uint32_t)(row * E_GROW + ch * 16);
            size_t gb = (size_t)row * HIDD + kt * 32 + ch * 8;
            CP16(base + E_BHI + so, Bhi + gb);
            CP16(base + E_BLO + so, Blo + gb);
        }
        // A: 64 rows x 4 chunks, hi (tid<256) / lo (tid>=256)
        {
            int row = (tid & 255) >> 2, ch = tid & 3;
            uint32_t so = (uint32_t)(row * E_GROW + ch * 16);
            size_t ga = (size_t)(m0 + row) * HIDD + kt * 32 + ch * 8;
            if (tid < 256) CP16(base + E_AHI + so, Ahi + ga);
            else           CP16(base + E_ALO + so, Alo + ga);
        }
        CP_COMMIT();
    };

    load_tile(0, 0);

    const int KT = HIDD / 32;  // 16
    for (int kt = 0; kt < KT; kt++) {
        if (kt + 1 < KT) {
            load_tile((kt + 1) & 1, kt + 1);
            cp_wait<1>();
        } else {
            cp_wait<0>();
        }
        __syncthreads();

        const uint32_t st = sb + (kt & 1) * E_STAGE;
        const uint32_t lrow = (uint32_t)(lane & 15);
        const uint32_t lcolB = (uint32_t)((lane >> 4) * 16);

        #pragma unroll
        for (int ks = 0; ks < 2; ks++) {
            const uint32_t kb = ks * 32 + lcolB;
            // A frags for both m16 tiles
            uint32_t ah[2][4], al[2][4];
            #pragma unroll
            for (int mt = 0; mt < 2; mt++) {
                uint32_t ro = (uint32_t)((wm * 32 + mt * 16 + lrow) * E_GROW) + kb;
                LDMX4(ah[mt][0], ah[mt][1], ah[mt][2], ah[mt][3], st + E_AHI + ro);
                LDMX4(al[mt][0], al[mt][1], al[mt][2], al[mt][3], st + E_ALO + ro);
            }
            #pragma unroll
            for (int p = 0; p < 4; p++) {   // n16 groups
                uint32_t ro = (uint32_t)((wn * 64 + p * 16 + lrow) * E_GROW) + kb;
                uint32_t bh0, bh1, bh2, bh3, bl0, bl1, bl2, bl3;
                LDMX4(bh0, bh1, bh2, bh3, st + E_BHI + ro);
                LDMX4(bl0, bl1, bl2, bl3, st + E_BLO + ro);
                #pragma unroll
                for (int mt = 0; mt < 2; mt++) {
                    #pragma unroll
                    for (int j = 0; j < 2; j++) {
                        float* cc = c[mt][p * 2 + j];
                        uint32_t b0 = j ? bh1 : bh0, b1 = j ? bh3 : bh2;
                        uint32_t l0 = j ? bl1 : bl0, l1 = j ? bl3 : bl2;
                        MMA16816(cc[0], cc[1], cc[2], cc[3],
                                 ah[mt][0], ah[mt][1], ah[mt][2], ah[mt][3], b0, b1);
                        MMA16816(cc[0], cc[1], cc[2], cc[3],
                                 ah[mt][0], ah[mt][1], ah[mt][2], ah[mt][3], l0, l1);
                        MMA16816(cc[0], cc[1], cc[2], cc[3],
                                 al[mt][0], al[mt][1], al[mt][2], al[mt][3], b0, b1);
                    }
                }
            }
        }
        __syncthreads();
    }

    // stage logits to smem (row stride 520 floats)
    #pragma unroll
    for (int mt = 0; mt < 2; mt++) {
        #pragma unroll
        for (int nt = 0; nt < 8; nt++) {
            #pragma unroll
            for (int i = 0; i < 2; i++) {
                int r = wm * 32 + mt * 16 + (lane >> 2) + i * 8;
                int col = wn * 64 + nt * 8 + (lane & 3) * 2;
                *(float2*)&sL[r * E_LSTRIDE + col] =
                    make_float2(c[mt][nt][i * 2], c[mt][nt][i * 2 + 1]);
            }
        }
    }
    __syncthreads();

    // each warp: 4 rows of softmax + final dot
    for (int rr = 0; rr < 4; rr++) {
        const int r = wid * 4 + rr;
        const int gm = m0 + r;
        const float* rowL = &sL[r * E_LSTRIDE];

        float lv[16];
        float mx = -3.4e38f;
        #pragma unroll
        for (int i = 0; i < 16; i++) {
            lv[i] = rowL[lane + 32 * i] * TEMP_INV;
            mx = fmaxf(mx, lv[i]);
        }
        #pragma unroll
        for (int m = 16; m > 0; m >>= 1) mx = fmaxf(mx, __shfl_xor_sync(FULL, mx, m));

        const __nv_bfloat16* hh = &g_Hhi[(size_t)gm * HIDD];
        const __nv_bfloat16* hl = &g_Hlo[(size_t)gm * HIDD];
        const float* bt = &beta[(size_t)gm * HIDD];

        float ssum = 0.0f, acc = 0.0f;
        #pragma unroll
        for (int i = 0; i < 16; i++) {
            int d = lane + 32 * i;
            float e = __expf(lv[i] - mx);
            ssum += e;
            float hd = __bfloat162float(hh[d]) + __bfloat162float(hl[d]);
            acc = fmaf(hd * e, bt[d] * sWo[d], acc);
        }
        float sd = sku[(size_t)gm * SKUD + lane] * g_WaWo[lane]
                 + sku[(size_t)gm * SKUD + 32 + lane] * g_WaWo[32 + lane];
        #pragma unroll
        for (int m = 16; m > 0; m >>= 1) {
            ssum += __shfl_xor_sync(FULL, ssum, m);
            acc  += __shfl_xor_sync(FULL, acc, m);
            sd   += __shfl_xor_sync(FULL, sd, m);
        }
        if (lane == 0) out[gm] = acc / ssum + sd;
    }
}

// ---------------- launch ----------------
extern "C" void kernel_launch(void* const* d_in, const int* in_sizes, int n_in,
                              void* d_out, int out_size) {
    const float* inputs   = (const float*)d_in[0];
    const float* sku      = (const float*)d_in[1];
    const float* deltas   = (const float*)d_in[2];
    const float* ln_gamma = (const float*)d_in[3];
    const float* ln_beta  = (const float*)d_in[4];
    const float* attn_w   = (const float*)d_in[5];
    const float* Wh       = (const float*)d_in[6];
    const float* Wah      = (const float*)d_in[7];
    const float* Waa      = (const float*)d_in[8];
    const float* Wb       = (const float*)d_in[9];
    const float* Wa       = (const float*)d_in[10];
    const float* Wo       = (const float*)d_in[11];
    float* out = (float*)d_out;

    __nv_bfloat16 *ahi, *alo, *hhi, *hlo, *skh, *skl;
    __nv_bfloat16 *wahh, *wahl, *waah, *waal, *wbh, *wbl;
    float *betab;
    cudaGetSymbolAddress((void**)&ahi, g_Ahi);
    cudaGetSymbolAddress((void**)&alo, g_Alo);
    cudaGetSymbolAddress((void**)&hhi, g_Hhi);
    cudaGetSymbolAddress((void**)&hlo, g_Hlo);
    cudaGetSymbolAddress((void**)&skh, g_skuhi);
    cudaGetSymbolAddress((void**)&skl, g_skulo);
    cudaGetSymbolAddress((void**)&wahh, g_WahT_hi);
    cudaGetSymbolAddress((void**)&wahl, g_WahT_lo);
    cudaGetSymbolAddress((void**)&waah, g_WaaT_hi);
    cudaGetSymbolAddress((void**)&waal, g_WaaT_lo);
    cudaGetSymbolAddress((void**)&wbh, g_WbT_hi);
    cudaGetSymbolAddress((void**)&wbl, g_WbT_lo);
    cudaGetSymbolAddress((void**)&betab, g_beta);

    cudaFuncSetAttribute(gemm_mma<1, true, false>, cudaFuncAttributeMaxDynamicSharedMemorySize, GEMM_SMEM);
    cudaFuncSetAttribute(gemm_mma<2, false, true>, cudaFuncAttributeMaxDynamicSharedMemorySize, GEMM_SMEM);
    cudaFuncSetAttribute(gemm2e, cudaFuncAttributeMaxDynamicSharedMemorySize, E_SMEM);

    prep_kernel<<<1, 512>>>(deltas, Wa, Wo);
    wconv_kernel<<<512, 128>>>(Wah, wahh, wahl, HIDD, HIDD);
    wconv_kernel<<<512, 128>>>(Waa, waah, waal, HIDD, HIDD);
    wconv_kernel<<<512, 64>>>(Wb, wbh, wbl, SKUD, HIDD);
    skuconv_kernel<<<(BB * SKUD) / 256, 256>>>(sku);

    dim3 g2(BB / 16, HH);
    rowfeat_kernel<<<g2, 512>>>(inputs, ln_gamma, ln_beta, attn_w, Wh);

    dim3 gg(4, BB / 128);
    gemm_mma<1, true, false><<<gg, 256, GEMM_SMEM>>>(ahi, alo, wahh, wahl, nullptr, hhi, hlo, HIDD);
    gemm_mma<2, false, true><<<gg, 256, GEMM_SMEM>>>(skh, skl, wbh, wbl, betab, nullptr, nullptr, SKUD);

    gemm2e<<<BB / 64, 512, E_SMEM>>>(hhi, hlo, waah, waal, betab, sku, Wo, out);
}

// round 5
// speedup vs baseline: 2.1078x; 1.2019x over previous
#include <cuda_runtime.h>
#include <cuda_fp16.h>
#include <cstdint>

// Problem constants
#define BB   131072
#define HH   16
#define CC   32
#define HIDD 512
#define HPP  32
#define SKUD 64
#define TEMP_INV (1.0f/0.7f)
#define TIME_MAX 365.0f
#define LN_EPS 1e-3f

// ---------------- scratch ----------------
__device__ __half g_A[(size_t)BB * HIDD];      // aggregated (fp16)
__device__ __half g_H[(size_t)BB * HIDD];      // agg_hidden (fp16)
__device__ float  g_beta[(size_t)BB * HIDD];   // sigmoid(sku@Wb)
__device__ __half g_sku[(size_t)BB * SKUD];    // sku (fp16)
__device__ __half g_WahT_hi[HIDD * HIDD], g_WahT_lo[HIDD * HIDD];
__device__ __half g_WaaT_hi[HIDD * HIDD], g_WaaT_lo[HIDD * HIDD];
__device__ __half g_WbT_hi[HIDD * SKUD], g_WbT_lo[HIDD * SKUD];
__device__ float g_cps[HH * CC];
__device__ float g_WaWo[SKUD];

// ---------------- helpers ----------------
__device__ __forceinline__ uint32_t smem_u32(const void* p) {
    uint32_t a;
    asm("{ .reg .u64 t; cvta.to.shared.u64 t, %1; cvt.u32.u64 %0, t; }" : "=r"(a) : "l"(p));
    return a;
}
#define CP16(dst, src) \
    asm volatile("cp.async.cg.shared.global [%0], [%1], 16;" :: "r"(dst), "l"(src))
#define CP_COMMIT() asm volatile("cp.async.commit_group;" ::: "memory")
template <int N>
__device__ __forceinline__ void cp_wait() {
    asm volatile("cp.async.wait_group %0;" :: "n"(N) : "memory");
}
#define LDMX4(d0, d1, d2, d3, addr) \
    asm volatile("ldmatrix.sync.aligned.m8n8.x4.shared.b16 {%0,%1,%2,%3}, [%4];" \
                 : "=r"(d0), "=r"(d1), "=r"(d2), "=r"(d3) : "r"(addr))
#define MMA16816(c0, c1, c2, c3, a0, a1, a2, a3, b0, b1) \
    asm volatile("mma.sync.aligned.m16n8k16.row.col.f32.f16.f16.f32 " \
                 "{%0,%1,%2,%3}, {%4,%5,%6,%7}, {%8,%9}, {%0,%1,%2,%3};" \
                 : "+f"(c0), "+f"(c1), "+f"(c2), "+f"(c3) \
                 : "r"(a0), "r"(a1), "r"(a2), "r"(a3), "r"(b0), "r"(b1))

__device__ __forceinline__ float softplusf(float x) {
    return fmaxf(x, 0.0f) + log1pf(expf(-fabsf(x)));
}
__device__ __forceinline__ float mishf(float x) {
    float t = __expf(fminf(x, 20.0f));
    float u = t * (t + 2.0f);
    float y = x * (u / (u + 2.0f));
    return (x > 20.0f) ? x : y;
}
__device__ __forceinline__ void split_fp16(float v, __half& hi, __half& lo) {
    hi = __float2half_rn(v);
    lo = __float2half_rn(v - __half2float(hi));
}

// ---------------- K1: prep ----------------
__global__ void prep_kernel(const float* __restrict__ deltas,
                            const float* __restrict__ Wa,
                            const float* __restrict__ Wo) {
    int tid = threadIdx.x;
    int warp = tid >> 5, lane = tid & 31;
    if (warp < HH) {
        float p = softplusf(deltas[warp * CC + lane]);
        #pragma unroll
        for (int off = 1; off < 32; off <<= 1) {
            float v = __shfl_up_sync(0xffffffffu, p, off);
            if (lane >= off) p += v;
        }
        float total = __shfl_sync(0xffffffffu, p, 31);
        g_cps[warp * CC + lane] = p / total * TIME_MAX;
    }
    if (tid < SKUD) {
        float acc = 0.0f;
        for (int d = 0; d < HIDD; d++) acc += Wa[tid * HIDD + d] * Wo[d];
        g_WaWo[tid] = acc;
    }
}

// ---------------- weight transpose + fp16 split ----------------
__global__ void wconv_kernel(const float* __restrict__ W,
                             __half* __restrict__ hi,
                             __half* __restrict__ lo, int K, int N) {
    int n = blockIdx.x;
    for (int k = threadIdx.x; k < K; k += blockDim.x) {
        float v = W[(size_t)k * N + n];
        __half h, l;
        split_fp16(v, h, l);
        hi[(size_t)n * K + k] = h;
        lo[(size_t)n * K + k] = l;
    }
}

__global__ void skuconv_kernel(const float* __restrict__ sku) {
    size_t i = (size_t)blockIdx.x * blockDim.x + threadIdx.x;
    if (i < (size_t)BB * SKUD)
        g_sku[i] = __float2half_rn(sku[i]);
}

// ---------------- K2: row features -> fp16 aggregated ----------------
__global__ void __launch_bounds__(512)
rowfeat_kernel(const float* __restrict__ inputs,
               const float* __restrict__ ln_gamma,
               const float* __restrict__ ln_beta,
               const float* __restrict__ attn_w,
               const float* __restrict__ Wh) {
    __shared__ float sWh[CC * HPP];
    __shared__ float sGamma[CC], sBeta[CC], sCps[CC];
    __shared__ float sAw;

    const int h = blockIdx.y;
    const int tid = threadIdx.x;

    for (int i = tid; i < CC * HPP; i += blockDim.x)
        sWh[i] = Wh[h * CC * HPP + i];
    if (tid < CC) {
        sGamma[tid] = ln_gamma[h * CC + tid];
        sBeta[tid]  = ln_beta[h * CC + tid];
        sCps[tid]   = g_cps[h * CC + tid];
    }
    if (tid == 0) sAw = attn_w[h];
    __syncthreads();

    const int warp = tid >> 5, lane = tid & 31;
    const int b = blockIdx.x * 16 + warp;
    const unsigned FULL = 0xffffffffu;

    float x = inputs[b * HH + h];
    float f = fmaxf(x - sCps[lane], 0.0f);

    float s = f;
    #pragma unroll
    for (int m = 16; m > 0; m >>= 1) s += __shfl_xor_sync(FULL, s, m);
    float mu = s * (1.0f / CC);
    float d = f - mu;
    float v = d * d;
    #pragma unroll
    for (int m = 16; m > 0; m >>= 1) v += __shfl_xor_sync(FULL, v, m);
    float var = v * (1.0f / CC);
    float normed = d * rsqrtf(var + LN_EPS) * sGamma[lane] + sBeta[lane];

    float logit = normed * sAw * TEMP_INV;
    float mx = logit;
    #pragma unroll
    for (int m = 16; m > 0; m >>= 1) mx = fmaxf(mx, __shfl_xor_sync(FULL, mx, m));
    float e = __expf(logit - mx);
    float es = e;
    #pragma unroll
    for (int m = 16; m > 0; m >>= 1) es += __shfl_xor_sync(FULL, es, m);
    float att = normed * (e / es);

    float acc = 0.0f;
    #pragma unroll
    for (int c = 0; c < CC; c++) {
        float av = __shfl_sync(FULL, att, c);
        acc = fmaf(av, sWh[c * HPP + lane], acc);
    }
    g_A[(size_t)b * HIDD + h * HPP + lane] = __float2half_rn(mishf(acc));
}

// ---------------- K3: tiled HMMA GEMM (gemm1 / gemm3) ----------------
// A fp16 single, B fp16 hi+lo, 2 MMA products. BM=128 BN=128 BK=32.
// 3-stage cp.async pipeline, 256 threads, 2 CTAs/SM.
#define GROW 80
#define S_A   0
#define S_BHI 10240
#define S_BLO 20480
#define STAGE 30720
#define GEMM_SMEM (3 * STAGE)   // 92160

template <int ACT, bool WRITE_HALF, bool WRITE_F32>
__global__ void __launch_bounds__(256, 2)
gemm_mma(const __half* __restrict__ A,
         const __half* __restrict__ Bhi, const __half* __restrict__ Blo,
         float* __restrict__ Cf, __half* __restrict__ Ch,
         int KG) {
    extern __shared__ char smem[];
    const uint32_t sb = smem_u32(smem);
    const int tid = threadIdx.x;
    const int wid = tid >> 5, lane = tid & 31;
    const int wm = wid & 1, wn = wid >> 1;
    const int m0 = blockIdx.y * 128;
    const int n0 = blockIdx.x * 128;
    const int KT = KG >> 5;

    float c[4][4][4];
    #pragma unroll
    for (int i = 0; i < 4; i++)
        #pragma unroll
        for (int j = 0; j < 4; j++)
            #pragma unroll
            for (int q = 0; q < 4; q++) c[i][j][q] = 0.0f;

    auto load_tile = [&](int s, int kt) {
        const uint32_t base = sb + s * STAGE;
        #pragma unroll
        for (int i = 0; i < 2; i++) {
            int idx = i * 256 + tid;
            int row = idx >> 2, ch = idx & 3;
            uint32_t so = (uint32_t)(row * GROW + ch * 16);
            size_t ga = (size_t)(m0 + row) * KG + kt * 32 + ch * 8;
            CP16(base + S_A + so, A + ga);
            size_t gb = (size_t)(n0 + row) * KG + kt * 32 + ch * 8;
            CP16(base + S_BHI + so, Bhi + gb);
            CP16(base + S_BLO + so, Blo + gb);
        }
        CP_COMMIT();
    };

    load_tile(0, 0);
    if (KT > 1) load_tile(1, 1);

    for (int kt = 0; kt < KT; kt++) {
        if (kt + 1 < KT) cp_wait<1>(); else cp_wait<0>();
        __syncthreads();
        if (kt + 2 < KT) load_tile((kt + 2) % 3, kt + 2);

        const uint32_t st = sb + (kt % 3) * STAGE;
        const uint32_t lrow = (uint32_t)(lane & 15);
        const uint32_t lcol = (uint32_t)((lane >> 4) * 16);

        #pragma unroll
        for (int ks = 0; ks < 2; ks++) {
            const uint32_t kb = ks * 32 + lcol;
            uint32_t bh[2][4], bl[2][4];
            #pragma unroll
            for (int p = 0; p < 2; p++) {
                uint32_t ro = (uint32_t)((wn * 32 + p * 16 + lrow) * GROW) + kb;
                LDMX4(bh[p][0], bh[p][1], bh[p][2], bh[p][3], st + S_BHI + ro);
                LDMX4(bl[p][0], bl[p][1], bl[p][2], bl[p][3], st + S_BLO + ro);
            }
            #pragma unroll
            for (int mt = 0; mt < 4; mt++) {
                uint32_t ro = (uint32_t)((wm * 64 + mt * 16 + lrow) * GROW) + kb;
                uint32_t a0, a1, a2, a3;
                LDMX4(a0, a1, a2, a3, st + S_A + ro);
                #pragma unroll
                for (int nt = 0; nt < 4; nt++) {
                    const int p = nt >> 1, j = nt & 1;
                    float* cc = c[mt][nt];
                    MMA16816(cc[0], cc[1], cc[2], cc[3],
                             a0, a1, a2, a3, bh[p][j], bh[p][j + 2]);
                    MMA16816(cc[0], cc[1], cc[2], cc[3],
                             a0, a1, a2, a3, bl[p][j], bl[p][j + 2]);
                }
            }
        }
        __syncthreads();
    }

    #pragma unroll
    for (int mt = 0; mt < 4; mt++) {
        #pragma unroll
        for (int nt = 0; nt < 4; nt++) {
            #pragma unroll
            for (int i = 0; i < 2; i++) {
                int gm = m0 + wm * 64 + mt * 16 + (lane >> 2) + i * 8;
                int gn = n0 + wn * 32 + nt * 8 + (lane & 3) * 2;
                float x0 = c[mt][nt][i * 2];
                float x1 = c[mt][nt][i * 2 + 1];
                if (ACT == 1) { x0 = mishf(x0); x1 = mishf(x1); }
                else if (ACT == 2) {
                    x0 = 1.0f / (1.0f + __expf(-x0));
                    x1 = 1.0f / (1.0f + __expf(-x1));
                }
                size_t o = (size_t)gm * HIDD + gn;
                if (WRITE_F32)
                    *(float2*)&Cf[o] = make_float2(x0, x1);
                if (WRITE_HALF)
                    *(__half2*)&Ch[o] =
                        __halves2half2(__float2half_rn(x0), __float2half_rn(x1));
            }
        }
    }
}

// ---------------- K4: fused GEMM2 + softmax epilogue ----------------
// BM=64, BN=512, BK=32, 512 threads (16 warps, 2x8), warp tile 32x64.
#define E_A   0
#define E_BHI 5120
#define E_BLO 46080
#define E_STAGE 87040
#define E_LSTRIDE 520
#define E_WO_OFF (2 * E_STAGE)            // 174080
#define E_SMEM (E_WO_OFF + 2048)          // 176128

__global__ void __launch_bounds__(512)
gemm2e(const __half* __restrict__ A,
       const __half* __restrict__ Bhi, const __half* __restrict__ Blo,
       const float* __restrict__ beta, const float* __restrict__ sku,
       const float* __restrict__ Wo, float* __restrict__ out) {
    extern __shared__ char smem[];
    const uint32_t sb = smem_u32(smem);
    float* sL = (float*)smem;
    float* sWo = (float*)(smem + E_WO_OFF);
    const int tid = threadIdx.x;
    const int wid = tid >> 5, lane = tid & 31;
    const int wm = wid & 1, wn = wid >> 1;
    const int m0 = blockIdx.x * 64;
    const unsigned FULL = 0xffffffffu;

    sWo[tid] = Wo[tid];

    float c[2][8][4];
    #pragma unroll
    for (int i = 0; i < 2; i++)
        #pragma unroll
        for (int j = 0; j < 8; j++)
            #pragma unroll
            for (int q = 0; q < 4; q++) c[i][j][q] = 0.0f;

    auto load_tile = [&](int s, int kt) {
        const uint32_t base = sb + s * E_STAGE;
        #pragma unroll
        for (int i = 0; i < 4; i++) {
            int idx = i * 512 + tid;
            int row = idx >> 2, ch = idx & 3;
            uint32_t so = (uint32_t)(row * GROW + ch * 16);
            size_t gb = (size_t)row * HIDD + kt * 32 + ch * 8;
            CP16(base + E_BHI + so, Bhi + gb);
            CP16(base + E_BLO + so, Blo + gb);
        }
        if (tid < 256) {
            int row = tid >> 2, ch = tid & 3;
            uint32_t so = (uint32_t)(row * GROW + ch * 16);
            size_t ga = (size_t)(m0 + row) * HIDD + kt * 32 + ch * 8;
            CP16(base + E_A + so, A + ga);
        }
        CP_COMMIT();
    };

    load_tile(0, 0);

    const int KT = HIDD / 32;
    for (int kt = 0; kt < KT; kt++) {
        if (kt + 1 < KT) {
            load_tile((kt + 1) & 1, kt + 1);
            cp_wait<1>();
        } else {
            cp_wait<0>();
        }
        __syncthreads();

        const uint32_t st = sb + (kt & 1) * E_STAGE;
        const uint32_t lrow = (uint32_t)(lane & 15);
        const uint32_t lcol = (uint32_t)((lane >> 4) * 16);

        #pragma unroll
        for (int ks = 0; ks < 2; ks++) {
            const uint32_t kb = ks * 32 + lcol;
            uint32_t a[2][4];
            #pragma unroll
            for (int mt = 0; mt < 2; mt++) {
                uint32_t ro = (uint32_t)((wm * 32 + mt * 16 + lrow) * GROW) + kb;
                LDMX4(a[mt][0], a[mt][1], a[mt][2], a[mt][3], st + E_A + ro);
            }
            #pragma unroll
            for (int p = 0; p < 4; p++) {
                uint32_t ro = (uint32_t)((wn * 64 + p * 16 + lrow) * GROW) + kb;
                uint32_t bh0, bh1, bh2, bh3, bl0, bl1, bl2, bl3;
                LDMX4(bh0, bh1, bh2, bh3, st + E_BHI + ro);
                LDMX4(bl0, bl1, bl2, bl3, st + E_BLO + ro);
                #pragma unroll
                for (int mt = 0; mt < 2; mt++) {
                    #pragma unroll
                    for (int j = 0; j < 2; j++) {
                        float* cc = c[mt][p * 2 + j];
                        uint32_t b0 = j ? bh1 : bh0, b1 = j ? bh3 : bh2;
                        uint32_t l0 = j ? bl1 : bl0, l1 = j ? bl3 : bl2;
                        MMA16816(cc[0], cc[1], cc[2], cc[3],
                                 a[mt][0], a[mt][1], a[mt][2], a[mt][3], b0, b1);
                        MMA16816(cc[0], cc[1], cc[2], cc[3],
                                 a[mt][0], a[mt][1], a[mt][2], a[mt][3], l0, l1);
                    }
                }
            }
        }
        __syncthreads();
    }

    #pragma unroll
    for (int mt = 0; mt < 2; mt++) {
        #pragma unroll
        for (int nt = 0; nt < 8; nt++) {
            #pragma unroll
            for (int i = 0; i < 2; i++) {
                int r = wm * 32 + mt * 16 + (lane >> 2) + i * 8;
                int col = wn * 64 + nt * 8 + (lane & 3) * 2;
                *(float2*)&sL[r * E_LSTRIDE + col] =
                    make_float2(c[mt][nt][i * 2], c[mt][nt][i * 2 + 1]);
            }
        }
    }
    __syncthreads();

    for (int rr = 0; rr < 4; rr++) {
        const int r = wid * 4 + rr;
        const int gm = m0 + r;
        const float* rowL = &sL[r * E_LSTRIDE];

        float lv[16];
        float mx = -3.4e38f;
        #pragma unroll
        for (int i = 0; i < 16; i++) {
            lv[i] = rowL[lane + 32 * i] * TEMP_INV;
            mx = fmaxf(mx, lv[i]);
        }
        #pragma unroll
        for (int m = 16; m > 0; m >>= 1) mx = fmaxf(mx, __shfl_xor_sync(FULL, mx, m));

        const __half* hh = &g_H[(size_t)gm * HIDD];
        const float* bt = &beta[(size_t)gm * HIDD];

        float ssum = 0.0f, acc = 0.0f;
        #pragma unroll
        for (int i = 0; i < 16; i++) {
            int d = lane + 32 * i;
            float e = __expf(lv[i] - mx);
            ssum += e;
            float hd = __half2float(hh[d]);
            acc = fmaf(hd * e, bt[d] * sWo[d], acc);
        }
        float sd = sku[(size_t)gm * SKUD + lane] * g_WaWo[lane]
                 + sku[(size_t)gm * SKUD + 32 + lane] * g_WaWo[32 + lane];
        #pragma unroll
        for (int m = 16; m > 0; m >>= 1) {
            ssum += __shfl_xor_sync(FULL, ssum, m);
            acc  += __shfl_xor_sync(FULL, acc, m);
            sd   += __shfl_xor_sync(FULL, sd, m);
        }
        if (lane == 0) out[gm] = acc / ssum + sd;
    }
}

// ---------------- launch ----------------
extern "C" void kernel_launch(void* const* d_in, const int* in_sizes, int n_in,
                              void* d_out, int out_size) {
    const float* inputs   = (const float*)d_in[0];
    const float* sku      = (const float*)d_in[1];
    const float* deltas   = (const float*)d_in[2];
    const float* ln_gamma = (const float*)d_in[3];
    const float* ln_beta  = (const float*)d_in[4];
    const float* attn_w   = (const float*)d_in[5];
    const float* Wh       = (const float*)d_in[6];
    const float* Wah      = (const float*)d_in[7];
    const float* Waa      = (const float*)d_in[8];
    const float* Wb       = (const float*)d_in[9];
    const float* Wa       = (const float*)d_in[10];
    const float* Wo       = (const float*)d_in[11];
    float* out = (float*)d_out;

    __half *a, *hdn, *skh;
    __half *wahh, *wahl, *waah, *waal, *wbh, *wbl;
    float *betab;
    cudaGetSymbolAddress((void**)&a, g_A);
    cudaGetSymbolAddress((void**)&hdn, g_H);
    cudaGetSymbolAddress((void**)&skh, g_sku);
    cudaGetSymbolAddress((void**)&wahh, g_WahT_hi);
    cudaGetSymbolAddress((void**)&wahl, g_WahT_lo);
    cudaGetSymbolAddress((void**)&waah, g_WaaT_hi);
    cudaGetSymbolAddress((void**)&waal, g_WaaT_lo);
    cudaGetSymbolAddress((void**)&wbh, g_WbT_hi);
    cudaGetSymbolAddress((void**)&wbl, g_WbT_lo);
    cudaGetSymbolAddress((void**)&betab, g_beta);

    cudaFuncSetAttribute(gemm_mma<1, true, false>, cudaFuncAttributeMaxDynamicSharedMemorySize, GEMM_SMEM);
    cudaFuncSetAttribute(gemm_mma<2, false, true>, cudaFuncAttributeMaxDynamicSharedMemorySize, GEMM_SMEM);
    cudaFuncSetAttribute(gemm2e, cudaFuncAttributeMaxDynamicSharedMemorySize, E_SMEM);

    prep_kernel<<<1, 512>>>(deltas, Wa, Wo);
    wconv_kernel<<<512, 128>>>(Wah, wahh, wahl, HIDD, HIDD);
    wconv_kernel<<<512, 128>>>(Waa, waah, waal, HIDD, HIDD);
    wconv_kernel<<<512, 64>>>(Wb, wbh, wbl, SKUD, HIDD);
    skuconv_kernel<<<(BB * SKUD) / 256, 256>>>(sku);

    dim3 g2(BB / 16, HH);
    rowfeat_kernel<<<g2, 512>>>(inputs, ln_gamma, ln_beta, attn_w, Wh);

    dim3 gg(4, BB / 128);
    gemm_mma<1, true, false><<<gg, 256, GEMM_SMEM>>>(a, wahh, wahl, nullptr, hdn, HIDD);
    gemm_mma<2, false, true><<<gg, 256, GEMM_SMEM>>>(skh, wbh, wbl, betab, nullptr, SKUD);

    gemm2e<<<BB / 64, 512, E_SMEM>>>(hdn, waah, waal, betab, sku, Wo, out);
}

// round 7
// speedup vs baseline: 2.6836x; 1.2732x over previous
#include <cuda_runtime.h>
#include <cuda_fp16.h>
#include <cstdint>

// Problem constants
#define BB   131072
#define HH   16
#define CC   32
#define HIDD 512
#define HPP  32
#define SKUD 64
#define TEMP_INV (1.0f/0.7f)
#define TIME_MAX 365.0f
#define LN_EPS 1e-3f

// ---------------- scratch ----------------
__device__ __half g_A[(size_t)BB * HIDD];      // aggregated (fp16)
__device__ __half g_H[(size_t)BB * HIDD];      // agg_hidden (fp16)
__device__ __half g_beta[(size_t)BB * HIDD];   // sigmoid(sku@Wb) (fp16)
__device__ __half g_sku[(size_t)BB * SKUD];    // sku (fp16)
__device__ __half g_WahT[HIDD * HIDD];
__device__ __half g_WaaT[HIDD * HIDD];
__device__ __half g_WbT[HIDD * SKUD];
__device__ float g_cps[HH * CC];
__device__ float g_WaWo[SKUD];

// ---------------- helpers ----------------
__device__ __forceinline__ uint32_t smem_u32(const void* p) {
    uint32_t a;
    asm("{ .reg .u64 t; cvta.to.shared.u64 t, %1; cvt.u32.u64 %0, t; }" : "=r"(a) : "l"(p));
    return a;
}
#define CP16(dst, src) \
    asm volatile("cp.async.cg.shared.global [%0], [%1], 16;" :: "r"(dst), "l"(src))
#define CP_COMMIT() asm volatile("cp.async.commit_group;" ::: "memory")
template <int N>
__device__ __forceinline__ void cp_wait() {
    asm volatile("cp.async.wait_group %0;" :: "n"(N) : "memory");
}
#define LDMX4(d0, d1, d2, d3, addr) \
    asm volatile("ldmatrix.sync.aligned.m8n8.x4.shared.b16 {%0,%1,%2,%3}, [%4];" \
                 : "=r"(d0), "=r"(d1), "=r"(d2), "=r"(d3) : "r"(addr))
#define MMA16816(c0, c1, c2, c3, a0, a1, a2, a3, b0, b1) \
    asm volatile("mma.sync.aligned.m16n8k16.row.col.f32.f16.f16.f32 " \
                 "{%0,%1,%2,%3}, {%4,%5,%6,%7}, {%8,%9}, {%0,%1,%2,%3};" \
                 : "+f"(c0), "+f"(c1), "+f"(c2), "+f"(c3) \
                 : "r"(a0), "r"(a1), "r"(a2), "r"(a3), "r"(b0), "r"(b1))

__device__ __forceinline__ float softplusf(float x) {
    return fmaxf(x, 0.0f) + log1pf(expf(-fabsf(x)));
}
__device__ __forceinline__ float mishf(float x) {
    float t = __expf(fminf(x, 20.0f));
    float u = t * (t + 2.0f);
    float y = x * (u / (u + 2.0f));
    return (x > 20.0f) ? x : y;
}

// ---------------- K1: prep ----------------
__global__ void prep_kernel(const float* __restrict__ deltas,
                            const float* __restrict__ Wa,
                            const float* __restrict__ Wo) {
    int tid = threadIdx.x;
    int warp = tid >> 5, lane = tid & 31;
    if (warp < HH) {
        float p = softplusf(deltas[warp * CC + lane]);
        #pragma unroll
        for (int off = 1; off < 32; off <<= 1) {
            float v = __shfl_up_sync(0xffffffffu, p, off);
            if (lane >= off) p += v;
        }
        float total = __shfl_sync(0xffffffffu, p, 31);
        g_cps[warp * CC + lane] = p / total * TIME_MAX;
    }
    if (tid < SKUD) {
        float acc = 0.0f;
        for (int d = 0; d < HIDD; d++) acc += Wa[tid * HIDD + d] * Wo[d];
        g_WaWo[tid] = acc;
    }
}

// ---------------- weight transpose + fp16 cast ----------------
__global__ void wconv_kernel(const float* __restrict__ W,
                             __half* __restrict__ o, int K, int N) {
    int n = blockIdx.x;
    for (int k = threadIdx.x; k < K; k += blockDim.x)
        o[(size_t)n * K + k] = __float2half_rn(W[(size_t)k * N + n]);
}

__global__ void skuconv_kernel(const float* __restrict__ sku) {
    size_t i = (size_t)blockIdx.x * blockDim.x + threadIdx.x;
    if (i < (size_t)BB * SKUD)
        g_sku[i] = __float2half_rn(sku[i]);
}

// ---------------- K2: row features -> fp16 aggregated ----------------
__global__ void __launch_bounds__(512)
rowfeat_kernel(const float* __restrict__ inputs,
               const float* __restrict__ ln_gamma,
               const float* __restrict__ ln_beta,
               const float* __restrict__ attn_w,
               const float* __restrict__ Wh) {
    __shared__ float sWh[CC * HPP];
    __shared__ float sGamma[CC], sBeta[CC], sCps[CC];
    __shared__ float sAw;

    const int h = blockIdx.y;
    const int tid = threadIdx.x;

    for (int i = tid; i < CC * HPP; i += blockDim.x)
        sWh[i] = Wh[h * CC * HPP + i];
    if (tid < CC) {
        sGamma[tid] = ln_gamma[h * CC + tid];
        sBeta[tid]  = ln_beta[h * CC + tid];
        sCps[tid]   = g_cps[h * CC + tid];
    }
    if (tid == 0) sAw = attn_w[h];
    __syncthreads();

    const int warp = tid >> 5, lane = tid & 31;
    const int b = blockIdx.x * 16 + warp;
    const unsigned FULL = 0xffffffffu;

    float x = inputs[b * HH + h];
    float f = fmaxf(x - sCps[lane], 0.0f);

    float s = f;
    #pragma unroll
    for (int m = 16; m > 0; m >>= 1) s += __shfl_xor_sync(FULL, s, m);
    float mu = s * (1.0f / CC);
    float d = f - mu;
    float v = d * d;
    #pragma unroll
    for (int m = 16; m > 0; m >>= 1) v += __shfl_xor_sync(FULL, v, m);
    float var = v * (1.0f / CC);
    float normed = d * rsqrtf(var + LN_EPS) * sGamma[lane] + sBeta[lane];

    float logit = normed * sAw * TEMP_INV;
    float mx = logit;
    #pragma unroll
    for (int m = 16; m > 0; m >>= 1) mx = fmaxf(mx, __shfl_xor_sync(FULL, mx, m));
    float e = __expf(logit - mx);
    float es = e;
    #pragma unroll
    for (int m = 16; m > 0; m >>= 1) es += __shfl_xor_sync(FULL, es, m);
    float att = normed * (e / es);

    float acc = 0.0f;
    #pragma unroll
    for (int c = 0; c < CC; c++) {
        float av = __shfl_sync(FULL, att, c);
        acc = fmaf(av, sWh[c * HPP + lane], acc);
    }
    g_A[(size_t)b * HIDD + h * HPP + lane] = __float2half_rn(mishf(acc));
}

// ---------------- K3: tiled HMMA GEMM (gemm1 / gemm3) ----------------
// Single fp16 product. BM=128 BN=128 BK=32. 3-stage cp.async, 256 thr, 2 CTAs/SM.
#define GROW 80
#define S_A  0
#define S_B  10240
#define STAGE 20480
#define GEMM_SMEM (3 * STAGE)   // 61440

template <int ACT>
__global__ void __launch_bounds__(256, 2)
gemm_mma(const __half* __restrict__ A, const __half* __restrict__ B,
         __half* __restrict__ C, int KG) {
    extern __shared__ char smem[];
    const uint32_t sb = smem_u32(smem);
    const int tid = threadIdx.x;
    const int wid = tid >> 5, lane = tid & 31;
    const int wm = wid & 1, wn = wid >> 1;
    const int m0 = blockIdx.y * 128;
    const int n0 = blockIdx.x * 128;
    const int KT = KG >> 5;

    float c[4][4][4];
    #pragma unroll
    for (int i = 0; i < 4; i++)
        #pragma unroll
        for (int j = 0; j < 4; j++)
            #pragma unroll
            for (int q = 0; q < 4; q++) c[i][j][q] = 0.0f;

    auto load_tile = [&](int s, int kt) {
        const uint32_t base = sb + s * STAGE;
        #pragma unroll
        for (int i = 0; i < 2; i++) {
            int idx = i * 256 + tid;
            int row = idx >> 2, ch = idx & 3;
            uint32_t so = (uint32_t)(row * GROW + ch * 16);
            size_t ga = (size_t)(m0 + row) * KG + kt * 32 + ch * 8;
            CP16(base + S_A + so, A + ga);
            size_t gb = (size_t)(n0 + row) * KG + kt * 32 + ch * 8;
            CP16(base + S_B + so, B + gb);
        }
        CP_COMMIT();
    };

    load_tile(0, 0);
    if (KT > 1) load_tile(1, 1);

    for (int kt = 0; kt < KT; kt++) {
        if (kt + 1 < KT) cp_wait<1>(); else cp_wait<0>();
        __syncthreads();
        if (kt + 2 < KT) load_tile((kt + 2) % 3, kt + 2);

        const uint32_t st = sb + (kt % 3) * STAGE;
        const uint32_t lrow = (uint32_t)(lane & 15);
        const uint32_t lcol = (uint32_t)((lane >> 4) * 16);

        #pragma unroll
        for (int ks = 0; ks < 2; ks++) {
            const uint32_t kb = ks * 32 + lcol;
            uint32_t bh[2][4];
            #pragma unroll
            for (int p = 0; p < 2; p++) {
                uint32_t ro = (uint32_t)((wn * 32 + p * 16 + lrow) * GROW) + kb;
                LDMX4(bh[p][0], bh[p][1], bh[p][2], bh[p][3], st + S_B + ro);
            }
            #pragma unroll
            for (int mt = 0; mt < 4; mt++) {
                uint32_t ro = (uint32_t)((wm * 64 + mt * 16 + lrow) * GROW) + kb;
                uint32_t a0, a1, a2, a3;
                LDMX4(a0, a1, a2, a3, st + S_A + ro);
                #pragma unroll
                for (int nt = 0; nt < 4; nt++) {
                    const int p = nt >> 1, j = nt & 1;
                    float* cc = c[mt][nt];
                    MMA16816(cc[0], cc[1], cc[2], cc[3],
                             a0, a1, a2, a3, bh[p][j], bh[p][j + 2]);
                }
            }
        }
        __syncthreads();
    }

    #pragma unroll
    for (int mt = 0; mt < 4; mt++) {
        #pragma unroll
        for (int nt = 0; nt < 4; nt++) {
            #pragma unroll
            for (int i = 0; i < 2; i++) {
                int gm = m0 + wm * 64 + mt * 16 + (lane >> 2) + i * 8;
                int gn = n0 + wn * 32 + nt * 8 + (lane & 3) * 2;
                float x0 = c[mt][nt][i * 2];
                float x1 = c[mt][nt][i * 2 + 1];
                if (ACT == 1) { x0 = mishf(x0); x1 = mishf(x1); }
                else if (ACT == 2) {
                    x0 = 1.0f / (1.0f + __expf(-x0));
                    x1 = 1.0f / (1.0f + __expf(-x1));
                }
                *(__half2*)&C[(size_t)gm * HIDD + gn] =
                    __halves2half2(__float2half_rn(x0), __float2half_rn(x1));
            }
        }
    }
}

// ---------------- K4: fused GEMM2 + softmax epilogue ----------------
// BM=64, BN=512, BK=32, 512 threads (16 warps, 2x8), warp tile 32x64.
#define E_A  0
#define E_B  5120
#define E_STAGE 46080
#define E_LSTRIDE 520
#define E_WO_OFF 133120                     // 64 * 520 * 4
#define E_SMEM (E_WO_OFF + 2048)            // 135168

__global__ void __launch_bounds__(512)
gemm2e(const __half* __restrict__ A, const __half* __restrict__ B,
       const __half* __restrict__ beta, const float* __restrict__ sku,
       const float* __restrict__ Wo, float* __restrict__ out) {
    extern __shared__ char smem[];
    const uint32_t sb = smem_u32(smem);
    float* sL = (float*)smem;
    float* sWo = (float*)(smem + E_WO_OFF);
    const int tid = threadIdx.x;
    const int wid = tid >> 5, lane = tid & 31;
    const int wm = wid & 1, wn = wid >> 1;
    const int m0 = blockIdx.x * 64;
    const unsigned FULL = 0xffffffffu;

    sWo[tid] = Wo[tid];

    float c[2][8][4];
    #pragma unroll
    for (int i = 0; i < 2; i++)
        #pragma unroll
        for (int j = 0; j < 8; j++)
            #pragma unroll
            for (int q = 0; q < 4; q++) c[i][j][q] = 0.0f;

    auto load_tile = [&](int s, int kt) {
        const uint32_t base = sb + s * E_STAGE;
        #pragma unroll
        for (int i = 0; i < 4; i++) {
            int idx = i * 512 + tid;
            int row = idx >> 2, ch = idx & 3;
            uint32_t so = (uint32_t)(row * GROW + ch * 16);
            size_t gb = (size_t)row * HIDD + kt * 32 + ch * 8;
            CP16(base + E_B + so, B + gb);
        }
        if (tid < 256) {
            int row = tid >> 2, ch = tid & 3;
            uint32_t so = (uint32_t)(row * GROW + ch * 16);
            size_t ga = (size_t)(m0 + row) * HIDD + kt * 32 + ch * 8;
            CP16(base + E_A + so, A + ga);
        }
        CP_COMMIT();
    };

    load_tile(0, 0);

    const int KT = HIDD / 32;
    for (int kt = 0; kt < KT; kt++) {
        if (kt + 1 < KT) {
            load_tile((kt + 1) & 1, kt + 1);
            cp_wait<1>();
        } else {
            cp_wait<0>();
        }
        __syncthreads();

        const uint32_t st = sb + (kt & 1) * E_STAGE;
        const uint32_t lrow = (uint32_t)(lane & 15);
        const uint32_t lcol = (uint32_t)((lane >> 4) * 16);

        #pragma unroll
        for (int ks = 0; ks < 2; ks++) {
            const uint32_t kb = ks * 32 + lcol;
            uint32_t a[2][4];
            #pragma unroll
            for (int mt = 0; mt < 2; mt++) {
                uint32_t ro = (uint32_t)((wm * 32 + mt * 16 + lrow) * GROW) + kb;
                LDMX4(a[mt][0], a[mt][1], a[mt][2], a[mt][3], st + E_A + ro);
            }
            #pragma unroll
            for (int p = 0; p < 4; p++) {
                uint32_t ro = (uint32_t)((wn * 64 + p * 16 + lrow) * GROW) + kb;
                uint32_t b0, b1, b2, b3;
                LDMX4(b0, b1, b2, b3, st + E_B + ro);
                #pragma unroll
                for (int mt = 0; mt < 2; mt++) {
                    float* c0 = c[mt][p * 2];
                    MMA16816(c0[0], c0[1], c0[2], c0[3],
                             a[mt][0], a[mt][1], a[mt][2], a[mt][3], b0, b2);
                    float* c1 = c[mt][p * 2 + 1];
                    MMA16816(c1[0], c1[1], c1[2], c1[3],
                             a[mt][0], a[mt][1], a[mt][2], a[mt][3], b1, b3);
                }
            }
        }
        __syncthreads();
    }

    #pragma unroll
    for (int mt = 0; mt < 2; mt++) {
        #pragma unroll
        for (int nt = 0; nt < 8; nt++) {
            #pragma unroll
            for (int i = 0; i < 2; i++) {
                int r = wm * 32 + mt * 16 + (lane >> 2) + i * 8;
                int col = wn * 64 + nt * 8 + (lane & 3) * 2;
                *(float2*)&sL[r * E_LSTRIDE + col] =
                    make_float2(c[mt][nt][i * 2], c[mt][nt][i * 2 + 1]);
            }
        }
    }
    __syncthreads();

    for (int rr = 0; rr < 4; rr++) {
        const int r = wid * 4 + rr;
        const int gm = m0 + r;
        const float* rowL = &sL[r * E_LSTRIDE];

        float lv[16];
        float mx = -3.4e38f;
        #pragma unroll
        for (int i = 0; i < 16; i++) {
            lv[i] = rowL[lane + 32 * i] * TEMP_INV;
            mx = fmaxf(mx, lv[i]);
        }
        #pragma unroll
        for (int m = 16; m > 0; m >>= 1) mx = fmaxf(mx, __shfl_xor_sync(FULL, mx, m));

        const __half* hh = &g_H[(size_t)gm * HIDD];
        const __half* bt = &g_beta[(size_t)gm * HIDD];

        float ssum = 0.0f, acc = 0.0f;
        #pragma unroll
        for (int i = 0; i < 16; i++) {
            int d = lane + 32 * i;
            float e = __expf(lv[i] - mx);
            ssum += e;
            float hd = __half2float(hh[d]);
            acc = fmaf(hd * e, __half2float(bt[d]) * sWo[d], acc);
        }
        float sd = sku[(size_t)gm * SKUD + lane] * g_WaWo[lane]
                 + sku[(size_t)gm * SKUD + 32 + lane] * g_WaWo[32 + lane];
        #pragma unroll
        for (int m = 16; m > 0; m >>= 1) {
            ssum += __shfl_xor_sync(FULL, ssum, m);
            acc  += __shfl_xor_sync(FULL, acc, m);
            sd   += __shfl_xor_sync(FULL, sd, m);
        }
        if (lane == 0) out[gm] = acc / ssum + sd;
    }
}

// ---------------- launch ----------------
extern "C" void kernel_launch(void* const* d_in, const int* in_sizes, int n_in,
                              void* d_out, int out_size) {
    const float* inputs   = (const float*)d_in[0];
    const float* sku      = (const float*)d_in[1];
    const float* deltas   = (const float*)d_in[2];
    const float* ln_gamma = (const float*)d_in[3];
    const float* ln_beta  = (const float*)d_in[4];
    const float* attn_w   = (const float*)d_in[5];
    const float* Wh       = (const float*)d_in[6];
    const float* Wah      = (const float*)d_in[7];
    const float* Waa      = (const float*)d_in[8];
    const float* Wb       = (const float*)d_in[9];
    const float* Wa       = (const float*)d_in[10];
    const float* Wo       = (const float*)d_in[11];
    float* out = (float*)d_out;

    __half *a, *hdn, *skh, *wah, *waa, *wb, *betab;
    cudaGetSymbolAddress((void**)&a, g_A);
    cudaGetSymbolAddress((void**)&hdn, g_H);
    cudaGetSymbolAddress((void**)&skh, g_sku);
    cudaGetSymbolAddress((void**)&wah, g_WahT);
    cudaGetSymbolAddress((void**)&waa, g_WaaT);
    cudaGetSymbolAddress((void**)&wb, g_WbT);
    cudaGetSymbolAddress((void**)&betab, g_beta);

    cudaFuncSetAttribute(gemm_mma<1>, cudaFuncAttributeMaxDynamicSharedMemorySize, GEMM_SMEM);
    cudaFuncSetAttribute(gemm_mma<2>, cudaFuncAttributeMaxDynamicSharedMemorySize, GEMM_SMEM);
    cudaFuncSetAttribute(gemm2e, cudaFuncAttributeMaxDynamicSharedMemorySize, E_SMEM);

    prep_kernel<<<1, 512>>>(deltas, Wa, Wo);
    wconv_kernel<<<512, 128>>>(Wah, wah, HIDD, HIDD);
    wconv_kernel<<<512, 128>>>(Waa, waa, HIDD, HIDD);
    wconv_kernel<<<512, 64>>>(Wb, wb, SKUD, HIDD);
    skuconv_kernel<<<(BB * SKUD) / 256, 256>>>(sku);

    dim3 g2(BB / 16, HH);
    rowfeat_kernel<<<g2, 512>>>(inputs, ln_gamma, ln_beta, attn_w, Wh);

    dim3 gg(4, BB / 128);
    gemm_mma<1><<<gg, 256, GEMM_SMEM>>>(a, wah, hdn, HIDD);
    gemm_mma<2><<<gg, 256, GEMM_SMEM>>>(skh, wb, betab, SKUD);

    gemm2e<<<BB / 64, 512, E_SMEM>>>(hdn, waa, betab, sku, Wo, out);
}